// round 2
// baseline (speedup 1.0000x reference)
#include <cuda_runtime.h>

// FCOS loss: B=16, C=80, P=21824 (16384+4096+1024+256+64), output = scalar mean.
// Input order (setup_inputs dict order):
//  0 confs    f32 (B,C,P)
//  1 locs     f32 (B,4,P)
//  2 centers  f32 (B,P)
//  3 tag_box  f32 (B,P,4)
//  4 center_t f32 (B,P)
//  5 pixel_xy f32 (P,2)
//  6 tag_class i32 (B,P)
//  7 status   i32 (B,P)

#define cB   16
#define cC   80
#define cP   21824
#define cP4  5456          // P/4
#define NB2  86            // ceil(P/256) blocks per image for box kernel

// Deterministic partial-sum scratch (no atomics, no init kernel needed:
// every slot is unconditionally written each launch).
__device__ float g_pconf[cB * cC];
__device__ float g_pl[cB * NB2];
__device__ float g_pc[cB * NB2];
__device__ float g_pn[cB * NB2];

// ---------------------------------------------------------------------------
// Focal loss element. Reference:
//   pos: -ALPHA*(1-p)^2*log(p)       neg: -(1-ALPHA)*p^2*log(1-p)
// Folded: q = pos?p:1-p, r = pos?1-p:p, coef = pos?0.25:0.75
//   loss = coef * r^2 * (-log(q))
// ---------------------------------------------------------------------------
__device__ __forceinline__ float focal_elem(float conf, bool pos) {
    float p    = fminf(fmaxf(conf, 1e-8f), 0.99999999f);
    float omp  = 1.0f - p;
    float q    = pos ? p   : omp;
    float r    = pos ? omp : p;
    float coef = pos ? 0.25f : 0.75f;
    return coef * r * r * (-__logf(q));
}

__global__ void __launch_bounds__(256) k_focal(const float4* __restrict__ confs,
                                               const int4*  __restrict__ tagc) {
    const int row = blockIdx.x;          // b*C + c
    const int b   = row / cC;
    const int c   = row % cC;
    const float4* crow = confs + (size_t)row * cP4;
    const int4*   trow = tagc  + (size_t)b   * cP4;

    float acc = 0.0f;
    #pragma unroll 2
    for (int i = threadIdx.x; i < cP4; i += 256) {
        float4 v = __ldg(&crow[i]);
        int4   t = __ldg(&trow[i]);
        acc += focal_elem(v.x, t.x == c);
        acc += focal_elem(v.y, t.y == c);
        acc += focal_elem(v.z, t.z == c);
        acc += focal_elem(v.w, t.w == c);
    }

    // block reduce
    #pragma unroll
    for (int o = 16; o; o >>= 1) acc += __shfl_down_sync(0xffffffffu, acc, o);
    __shared__ float sm[8];
    if ((threadIdx.x & 31) == 0) sm[threadIdx.x >> 5] = acc;
    __syncthreads();
    if (threadIdx.x == 0) {
        float s = 0.0f;
        #pragma unroll
        for (int w = 0; w < 8; w++) s += sm[w];
        g_pconf[row] = s;
    }
}

// ---------------------------------------------------------------------------
// Per-anchor IoU-log loss + centerness BCE + positive count. Only status==1
// anchors contribute (reference multiplies by pos), so loads are gated.
// ---------------------------------------------------------------------------
__global__ void __launch_bounds__(256) k_box(
    const float* __restrict__ locs,     const float* __restrict__ centers,
    const float* __restrict__ tag_box,  const float* __restrict__ center_t,
    const float* __restrict__ pixel_xy, const int*   __restrict__ status)
{
    const int b = blockIdx.y;
    const int p = blockIdx.x * 256 + threadIdx.x;

    float ll = 0.0f, lc = 0.0f, np = 0.0f;
    if (p < cP && status[b * cP + p] != 0) {
        float x = pixel_xy[2 * p];
        float y = pixel_xy[2 * p + 1];
        const float* lrow = locs + (size_t)b * 4 * cP;
        float pl = x - lrow[p];
        float pt = y - lrow[cP + p];
        float pr = x + lrow[2 * cP + p];
        float pb = y + lrow[3 * cP + p];

        const float* tbx = tag_box + ((size_t)b * cP + p) * 4;
        float tl = tbx[0], tt = tbx[1], tr = tbx[2], tb = tbx[3];

        float s1 = (tb - tt + 1.0f) * (tr - tl + 1.0f);
        float s2 = (pb - pt + 1.0f) * (pr - pl + 1.0f);
        float clx = fmaxf(tl, pl), crx = fminf(tr, pr);
        float cty = fmaxf(tt, pt), cby = fminf(tb, pb);
        float sc  = (crx - clx + 1.0f) * (cby - cty + 1.0f);
        float un  = s1 + s2 - sc;
        bool valid = (clx < crx) && (cty < cby) && (sc > 0.0f) && (un > 0.0f);
        ll = valid ? -logf(sc / un) : 0.0f;

        float cen = centers[b * cP + p];
        float ct_ = center_t[b * cP + p];
        float bce = -(ct_ * fmaxf(logf(cen), -100.0f)
                      + (1.0f - ct_) * fmaxf(log1pf(-cen), -100.0f));
        lc = bce;
        np = 1.0f;
    }

    // block reduce the three accumulators
    #pragma unroll
    for (int o = 16; o; o >>= 1) {
        ll += __shfl_down_sync(0xffffffffu, ll, o);
        lc += __shfl_down_sync(0xffffffffu, lc, o);
        np += __shfl_down_sync(0xffffffffu, np, o);
    }
    __shared__ float s0[8], s1s[8], s2s[8];
    if ((threadIdx.x & 31) == 0) {
        int w = threadIdx.x >> 5;
        s0[w] = ll; s1s[w] = lc; s2s[w] = np;
    }
    __syncthreads();
    if (threadIdx.x == 0) {
        float a = 0.f, bsum = 0.f, cc = 0.f;
        #pragma unroll
        for (int w = 0; w < 8; w++) { a += s0[w]; bsum += s1s[w]; cc += s2s[w]; }
        int idx = b * NB2 + blockIdx.x;
        g_pl[idx] = a; g_pc[idx] = bsum; g_pn[idx] = cc;
    }
}

// ---------------------------------------------------------------------------
// Final deterministic combine: 16 warps, one per image.
// ---------------------------------------------------------------------------
__global__ void __launch_bounds__(512) k_final(float* __restrict__ out) {
    const int w    = threadIdx.x >> 5;   // image 0..15
    const int lane = threadIdx.x & 31;

    float conf = 0.f, ll = 0.f, lc = 0.f, np = 0.f;
    for (int i = lane; i < cC; i += 32) conf += g_pconf[w * cC + i];
    for (int i = lane; i < NB2; i += 32) {
        ll += g_pl[w * NB2 + i];
        lc += g_pc[w * NB2 + i];
        np += g_pn[w * NB2 + i];
    }
    #pragma unroll
    for (int o = 16; o; o >>= 1) {
        conf += __shfl_down_sync(0xffffffffu, conf, o);
        ll   += __shfl_down_sync(0xffffffffu, ll, o);
        lc   += __shfl_down_sync(0xffffffffu, lc, o);
        np   += __shfl_down_sync(0xffffffffu, np, o);
    }
    __shared__ float simg[cB];
    if (lane == 0) {
        float s = conf + ll;
        simg[w] = (np > 0.0f) ? (lc + s / fmaxf(np, 1.0f)) : (lc + s);
    }
    __syncthreads();
    if (threadIdx.x == 0) {
        float t = 0.0f;
        #pragma unroll
        for (int i = 0; i < cB; i++) t += simg[i];
        *out = t * (1.0f / (float)cB);
    }
}

extern "C" void kernel_launch(void* const* d_in, const int* in_sizes, int n_in,
                              void* d_out, int out_size) {
    (void)in_sizes; (void)n_in; (void)out_size;
    const float* confs    = (const float*)d_in[0];
    const float* locs     = (const float*)d_in[1];
    const float* centers  = (const float*)d_in[2];
    const float* tag_box  = (const float*)d_in[3];
    const float* center_t = (const float*)d_in[4];
    const float* pixel_xy = (const float*)d_in[5];
    const int*   tag_class= (const int*)  d_in[6];
    const int*   status   = (const int*)  d_in[7];

    k_focal<<<cB * cC, 256>>>((const float4*)confs, (const int4*)tag_class);
    dim3 g2(NB2, cB);
    k_box<<<g2, 256>>>(locs, centers, tag_box, center_t, pixel_xy, status);
    k_final<<<1, 512>>>((float*)d_out);
}

// round 3
// speedup vs baseline: 1.2630x; 1.2630x over previous
#include <cuda_runtime.h>

// FCOS loss: B=16, C=80, P=21824 (16384+4096+1024+256+64), output = scalar mean.
// Inputs: 0 confs f32(B,C,P) 1 locs f32(B,4,P) 2 centers f32(B,P) 3 tag_box f32(B,P,4)
//         4 center_t f32(B,P) 5 pixel_xy f32(P,2) 6 tag_class i32(B,P) 7 status i32(B,P)

#define cB   16
#define cC   80
#define cP   21824
#define cP4  5456
#define FBLK 74                     // focal blocks per image
#define BBLK 22                     // box blocks per image
#define BOXSPAN 992                 // anchors per box block (22*992 = 21824)
#define NTH  256
#define STRIDE (FBLK*NTH)           // 18944 threads per image (focal)
#define PERB (cC*cP4)               // 436480 float4 items per image
#define NFULL 23                    // 18944*23 = 435712; remainder 768
#define KSCALE (-0.519860385f)      // -0.75 * ln(2)

// Deterministic partial sums (every slot written unconditionally each launch).
__device__ float g_pconf[cB * FBLK];
__device__ float g_pl[cB * BBLK];
__device__ float g_pc[cB * BBLK];
__device__ float g_pn[cB * BBLK];

__device__ __forceinline__ float clampp(float v) {
    return fminf(fmaxf(v, 1e-8f), 0.99999999f);
}
// negative-class focal term:  -(1-ALPHA) * p^2 * log(1-p)
__device__ __forceinline__ float neg_f(float v) {
    float p = clampp(v);
    return 0.75f * p * p * (-__logf(1.0f - p));
}
// positive-class focal term:  -ALPHA * (1-p)^2 * log(p)
__device__ __forceinline__ float pos_f(float v) {
    float p = clampp(v);
    float o = 1.0f - p;
    return 0.25f * o * o * (-__logf(p));
}
// streaming focal element, unscaled: p^2 * log2(1-p)  (multiply by KSCALE later)
__device__ __forceinline__ float felem(float v) {
    float p = clampp(v);
    return (p * p) * __log2f(1.0f - p);
}

__global__ void __launch_bounds__(256) k_main(
    const float* __restrict__ confs,    const float* __restrict__ locs,
    const float* __restrict__ centers,  const float* __restrict__ tag_box,
    const float* __restrict__ center_t, const float* __restrict__ pixel_xy,
    const int*   __restrict__ tag_class,const int*   __restrict__ status)
{
    const int b = blockIdx.y;
    __shared__ float s0[8], s1[8], s2[8];

    if (blockIdx.x < FBLK) {
        // ----- pure streaming focal reduction over (C,P) for image b -----
        const float4* base = (const float4*)confs + (size_t)b * PERB;
        int j = blockIdx.x * NTH + threadIdx.x;
        float a0 = 0.f, a1 = 0.f, a2 = 0.f, a3 = 0.f;
        #pragma unroll 1
        for (int it = 0; it < NFULL / 4; ++it) {        // 5 iterations of 4
            float4 v0 = __ldg(base + j);
            float4 v1 = __ldg(base + j + STRIDE);
            float4 v2 = __ldg(base + j + 2 * STRIDE);
            float4 v3 = __ldg(base + j + 3 * STRIDE);
            a0 += felem(v0.x) + felem(v0.y) + felem(v0.z) + felem(v0.w);
            a1 += felem(v1.x) + felem(v1.y) + felem(v1.z) + felem(v1.w);
            a2 += felem(v2.x) + felem(v2.y) + felem(v2.z) + felem(v2.w);
            a3 += felem(v3.x) + felem(v3.y) + felem(v3.z) + felem(v3.w);
            j += 4 * STRIDE;
        }
        #pragma unroll
        for (int it = 0; it < NFULL % 4; ++it) {        // 3 more full iters
            float4 v = __ldg(base + j);
            a0 += felem(v.x) + felem(v.y) + felem(v.z) + felem(v.w);
            j += STRIDE;
        }
        if (j < PERB) {                                  // 768-item remainder
            float4 v = __ldg(base + j);
            a1 += felem(v.x) + felem(v.y) + felem(v.z) + felem(v.w);
        }
        float acc = (a0 + a1) + (a2 + a3);
        #pragma unroll
        for (int o = 16; o; o >>= 1) acc += __shfl_down_sync(0xffffffffu, acc, o);
        if ((threadIdx.x & 31) == 0) s0[threadIdx.x >> 5] = acc;
        __syncthreads();
        if (threadIdx.x == 0) {
            float s = 0.f;
            #pragma unroll
            for (int w = 0; w < 8; w++) s += s0[w];
            g_pconf[b * FBLK + blockIdx.x] = s * KSCALE;
        }
    } else {
        // ----- per-anchor: focal positive-class correction + IoU + BCE -----
        const int bx = blockIdx.x - FBLK;
        float ll = 0.f, lc = 0.f, np = 0.f;
        #pragma unroll 1
        for (int k = 0; k < 4; ++k) {
            int off = k * NTH + threadIdx.x;
            if (off >= BOXSPAN) break;
            int p = bx * BOXSPAN + off;
            int bp = b * cP + p;

            int t = tag_class[bp];
            if (t < cC) {   // tagged channel: replace its neg term with pos term
                float pf = confs[((size_t)b * cC + t) * cP + p];
                ll += pos_f(pf) - neg_f(pf);
            }
            if (status[bp] != 0) {
                float x = pixel_xy[2 * p];
                float y = pixel_xy[2 * p + 1];
                const float* lrow = locs + (size_t)b * 4 * cP;
                float pl = x - lrow[p];
                float pt = y - lrow[cP + p];
                float pr = x + lrow[2 * cP + p];
                float pb = y + lrow[3 * cP + p];
                const float* tbx = tag_box + (size_t)bp * 4;
                float tl = tbx[0], tt = tbx[1], tr = tbx[2], tb = tbx[3];
                float sA = (tb - tt + 1.0f) * (tr - tl + 1.0f);
                float sB = (pb - pt + 1.0f) * (pr - pl + 1.0f);
                float clx = fmaxf(tl, pl), crx = fminf(tr, pr);
                float cty = fmaxf(tt, pt), cby = fminf(tb, pb);
                float sc  = (crx - clx + 1.0f) * (cby - cty + 1.0f);
                float un  = sA + sB - sc;
                bool valid = (clx < crx) && (cty < cby) && (sc > 0.0f) && (un > 0.0f);
                if (valid) ll += -logf(sc / un);
                float cen = centers[bp];
                float ct_ = center_t[bp];
                lc += -(ct_ * fmaxf(logf(cen), -100.0f)
                        + (1.0f - ct_) * fmaxf(log1pf(-cen), -100.0f));
                np += 1.0f;
            }
        }
        #pragma unroll
        for (int o = 16; o; o >>= 1) {
            ll += __shfl_down_sync(0xffffffffu, ll, o);
            lc += __shfl_down_sync(0xffffffffu, lc, o);
            np += __shfl_down_sync(0xffffffffu, np, o);
        }
        if ((threadIdx.x & 31) == 0) {
            int w = threadIdx.x >> 5;
            s0[w] = ll; s1[w] = lc; s2[w] = np;
        }
        __syncthreads();
        if (threadIdx.x == 0) {
            float a = 0.f, c2 = 0.f, n2 = 0.f;
            #pragma unroll
            for (int w = 0; w < 8; w++) { a += s0[w]; c2 += s1[w]; n2 += s2[w]; }
            int idx = b * BBLK + bx;
            g_pl[idx] = a; g_pc[idx] = c2; g_pn[idx] = n2;
        }
    }
}

// Final deterministic combine: 16 warps, one per image.
__global__ void __launch_bounds__(512) k_final(float* __restrict__ out) {
    const int w    = threadIdx.x >> 5;
    const int lane = threadIdx.x & 31;

    float conf = 0.f, ll = 0.f, lc = 0.f, np = 0.f;
    for (int i = lane; i < FBLK; i += 32) conf += g_pconf[w * FBLK + i];
    if (lane < BBLK) {
        ll = g_pl[w * BBLK + lane];
        lc = g_pc[w * BBLK + lane];
        np = g_pn[w * BBLK + lane];
    }
    #pragma unroll
    for (int o = 16; o; o >>= 1) {
        conf += __shfl_down_sync(0xffffffffu, conf, o);
        ll   += __shfl_down_sync(0xffffffffu, ll, o);
        lc   += __shfl_down_sync(0xffffffffu, lc, o);
        np   += __shfl_down_sync(0xffffffffu, np, o);
    }
    __shared__ float simg[cB];
    if (lane == 0) {
        float s = conf + ll;
        simg[w] = (np > 0.0f) ? (lc + s / fmaxf(np, 1.0f)) : (lc + s);
    }
    __syncthreads();
    if (threadIdx.x == 0) {
        float t = 0.0f;
        #pragma unroll
        for (int i = 0; i < cB; i++) t += simg[i];
        *out = t * (1.0f / (float)cB);
    }
}

extern "C" void kernel_launch(void* const* d_in, const int* in_sizes, int n_in,
                              void* d_out, int out_size) {
    (void)in_sizes; (void)n_in; (void)out_size;
    const float* confs    = (const float*)d_in[0];
    const float* locs     = (const float*)d_in[1];
    const float* centers  = (const float*)d_in[2];
    const float* tag_box  = (const float*)d_in[3];
    const float* center_t = (const float*)d_in[4];
    const float* pixel_xy = (const float*)d_in[5];
    const int*   tag_class= (const int*)  d_in[6];
    const int*   status   = (const int*)  d_in[7];

    dim3 grid(FBLK + BBLK, cB);
    k_main<<<grid, NTH>>>(confs, locs, centers, tag_box, center_t,
                          pixel_xy, tag_class, status);
    k_final<<<1, 512>>>((float*)d_out);
}